// round 14
// baseline (speedup 1.0000x reference)
#include <cuda_runtime.h>
#include <cuda_bf16.h>
#include <cstdint>
#include <math.h>

#define NQ 4
#define NL 3
#define DIM 16

// Pair-major W fragments: for MMA pair p (vr tile nt=p, vi tile nt=p+2),
// thread (g,t) loads ONE uint4:
//   .x = {Re[p*8+g][2t],   Re[p*8+g][2t+1]}   (bf16x2)
//   .y = {Re[p*8+g][2t+8], Re[p*8+g][2t+9]}
//   .z = {Im[p*8+g][2t],   Im[p*8+g][2t+1]}
//   .w = {Im[p*8+g][2t+8], Im[p*8+g][2t+9]}
__device__ uint4 g_Wp_h[2][8][4];   // [pair][g][t]  hi part
__device__ uint4 g_Wp_l[2][8][4];   //               lo (residual) part

// hi/lo bf16 split of a float pair, packed {v0 -> lo half, v1 -> hi half}
__device__ __forceinline__ void split2(float v0, float v1,
                                       uint32_t& h, uint32_t& l) {
    asm("cvt.rn.bf16x2.f32 %0, %1, %2;" : "=r"(h) : "f"(v1), "f"(v0));
    float f0 = __uint_as_float(h << 16);
    float f1 = __uint_as_float(h & 0xFFFF0000u);
    float l0 = v0 - f0;
    float l1 = v1 - f1;
    asm("cvt.rn.bf16x2.f32 %0, %1, %2;" : "=r"(l) : "f"(l1), "f"(l0));
}

// ---------------------------------------------------------------------------
// Prekernel: 256 threads = 16 columns x 16 basis states, one complex
// amplitude per thread (shfl_xor butterflies). Then 64 threads repack U into
// the pair-major W fragment layout.
// ---------------------------------------------------------------------------
__global__ void precompute_W_kernel(const float* __restrict__ params) {
    __shared__ float sUr[DIM][DIM], sUi[DIM][DIM];

    const int tid = threadIdx.x;          // 0..255
    const int j = tid >> 4;               // column (initial basis state)
    const int i = tid & 15;               // this thread's basis state index

    float re = (i == j) ? 1.0f : 0.0f;
    float im = 0.0f;

#pragma unroll
    for (int l = 0; l < NL; l++) {
#pragma unroll
        for (int w = 0; w < NQ; w++) {
            const int m = 1 << (3 - w);
            float ty = 0.5f * params[(l * NQ + w) * 2 + 0];
            float sy, cy;
            __sincosf(ty, &sy, &cy);
            float pre = __shfl_xor_sync(0xFFFFFFFFu, re, m);
            float pim = __shfl_xor_sync(0xFFFFFFFFu, im, m);
            if (i & m) {
                re = fmaf(cy, re,  sy * pre);
                im = fmaf(cy, im,  sy * pim);
            } else {
                re = fmaf(cy, re, -sy * pre);
                im = fmaf(cy, im, -sy * pim);
            }
            float tz = 0.5f * params[(l * NQ + w) * 2 + 1];
            float sz, cz;
            __sincosf(tz, &sz, &cz);
            float szs = (i & m) ? sz : -sz;
            float nre = fmaf(cz, re, -szs * im);
            float nim = fmaf(cz, im,  szs * re);
            re = nre;
            im = nim;
        }
#pragma unroll
        for (int w = 0; w < NQ - 1; w++) {
            const int mc = 1 << (3 - w);
            const int mt = 1 << (2 - w);
            float pre = __shfl_xor_sync(0xFFFFFFFFu, re, mt);
            float pim = __shfl_xor_sync(0xFFFFFFFFu, im, mt);
            if (i & mc) { re = pre; im = pim; }
        }
    }

    sUr[i][j] = re;
    sUi[i][j] = im;
    __syncthreads();

    // Repack: 64 threads, one uint4 pair-entry each.
    if (tid < 64) {
        const int p = (tid >> 5) & 1;
        const int g = (tid >> 2) & 7;
        const int t = tid & 3;
        const int n = p * 8 + g;   // U row
        const int k0 = 2 * t;

        uint4 h, l;
        split2(sUr[n][k0],     sUr[n][k0 + 1], h.x, l.x);
        split2(sUr[n][k0 + 8], sUr[n][k0 + 9], h.y, l.y);
        split2(sUi[n][k0],     sUi[n][k0 + 1], h.z, l.z);
        split2(sUi[n][k0 + 8], sUi[n][k0 + 9], h.w, l.w);
        g_Wp_h[p][g][t] = h;
        g_Wp_l[p][g][t] = l;
    }
}

// ---------------------------------------------------------------------------
// HMMA helpers (base-target sm_80+ instructions; no 'a' features)
// ---------------------------------------------------------------------------
__device__ __forceinline__ uint32_t smem_u32(const void* p) {
    uint32_t a;
    asm("{ .reg .u64 t; cvta.to.shared.u64 t, %1; cvt.u32.u64 %0, t; }"
        : "=r"(a) : "l"(p));
    return a;
}

__device__ __forceinline__ void ldmatrix_x4(uint32_t& r0, uint32_t& r1,
                                            uint32_t& r2, uint32_t& r3,
                                            uint32_t addr) {
    asm volatile("ldmatrix.sync.aligned.m8n8.x4.shared.b16 {%0,%1,%2,%3}, [%4];"
                 : "=r"(r0), "=r"(r1), "=r"(r2), "=r"(r3) : "r"(addr));
}

__device__ __forceinline__ void mma_bf16(float* d, uint32_t a0, uint32_t a1,
                                         uint32_t a2, uint32_t a3,
                                         uint32_t b0, uint32_t b1) {
    asm volatile(
        "mma.sync.aligned.m16n8k16.row.col.f32.bf16.bf16.f32 "
        "{%0,%1,%2,%3}, {%4,%5,%6,%7}, {%8,%9}, {%0,%1,%2,%3};"
        : "+f"(d[0]), "+f"(d[1]), "+f"(d[2]), "+f"(d[3])
        : "r"(a0), "r"(a1), "r"(a2), "r"(a3), "r"(b0), "r"(b1));
}

__device__ __forceinline__ void mma_bf16_k8(float* d, uint32_t a0, uint32_t a1,
                                            uint32_t b0) {
    asm volatile(
        "mma.sync.aligned.m16n8k8.row.col.f32.bf16.bf16.f32 "
        "{%0,%1,%2,%3}, {%4,%5}, {%6}, {%0,%1,%2,%3};"
        : "+f"(d[0]), "+f"(d[1]), "+f"(d[2]), "+f"(d[3])
        : "r"(a0), "r"(a1), "r"(b0));
}

// ---------------------------------------------------------------------------
// Main kernel: 64 items/warp as two sequential 32-item groups reusing one
// 16KB staging buffer. Per tile, (vr,vi) tile PAIRS are processed together:
// pair p -> 6 V-MMAs -> pr -> split -> 2 k8 EV-MMAs. Live register set drops
// to ~35 so the (256,5) cap (48 regs) fits without spills.
// ---------------------------------------------------------------------------
__global__ __launch_bounds__(256, 5) void vqc_hmma_kernel(
    const float4* __restrict__ patch, float4* __restrict__ out, int n) {
    // per-warp staging: [8 warps][hi/lo][32 rows][8 u32]  (16 KB)
    __shared__ __align__(16) uint32_t stage[8][2][32][8];

    const int tid = threadIdx.x;
    const int wid = tid >> 5;
    const int lane = tid & 31;
    const int g = lane >> 2;      // 0..7
    const int t = lane & 3;       // 0..3

    const int itemBase = blockIdx.x * 512 + wid * 64;

    // ---- sign-matrix k8 B fragments (Z[k=i][n=w], exact +-1 bf16) ----
    uint32_t bs0, bs1;
    {
        auto enc = [&](int i) -> uint32_t {
            if (g >= 4) return 0u;  // unused n columns
            return (((i >> (3 - g)) & 1) ? 0xBF80u : 0x3F80u);
        };
        bs0 = enc(2 * t) | (enc(2 * t + 1) << 16);       // i-block 0 (i=2t,2t+1)
        bs1 = enc(2 * t + 8) | (enc(2 * t + 9) << 16);   // i-block 1 (i=8+2t,..)
    }

    float2* o2 = reinterpret_cast<float2*>(out);

#pragma unroll
    for (int u = 0; u < 2; u++) {
        // ---- load this group's patch and build s[16] hi/lo, stage row=lane --
        {
            int item = itemBase + u * 32 + lane;
            float4 p = patch[item < n ? item : (n - 1)];
            float s0, c0, s1, c1, s2, c2, s3, c3;
            __sincosf(0.5f * p.x, &s0, &c0);
            __sincosf(0.5f * p.y, &s1, &c1);
            __sincosf(0.5f * p.z, &s2, &c2);
            __sincosf(0.5f * p.w, &s3, &c3);
            float qa[4] = {c0 * c1, c0 * s1, s0 * c1, s0 * s1};
            float qb[4] = {c2 * c3, c2 * s3, s2 * c3, s2 * s3};

            uint32_t hi[8], lo[8];
#pragma unroll
            for (int c = 0; c < 8; c++) {
                int k0 = 2 * c, k1 = 2 * c + 1;
                float v0 = qa[k0 >> 2] * qb[k0 & 3];
                float v1 = qa[k1 >> 2] * qb[k1 & 3];
                split2(v0, v1, hi[c], lo[c]);
            }
            uint4* dh = reinterpret_cast<uint4*>(&stage[wid][0][lane][0]);
            uint4* dl = reinterpret_cast<uint4*>(&stage[wid][1][lane][0]);
            dh[0] = make_uint4(hi[0], hi[1], hi[2], hi[3]);
            dh[1] = make_uint4(hi[4], hi[5], hi[6], hi[7]);
            dl[0] = make_uint4(lo[0], lo[1], lo[2], lo[3]);
            dl[1] = make_uint4(lo[4], lo[5], lo[6], lo[7]);
        }
        __syncwarp();

#pragma unroll
        for (int sl = 0; sl < 2; sl++) {
            const int s = u * 2 + sl;     // global tile index (item block)
            uint32_t ah0, ah1, ah2, ah3, al0, al1, al2, al3;
            {
                int mrow = sl * 16 + (lane & 15);
                int chunk = (lane >> 4);
                uint32_t addrh = smem_u32(&stage[wid][0][mrow][chunk * 4]);
                uint32_t addrl = smem_u32(&stage[wid][1][mrow][chunk * 4]);
                ldmatrix_x4(ah0, ah1, ah2, ah3, addrh);
                ldmatrix_x4(al0, al1, al2, al3, addrl);
            }

            float ev[4] = {0.0f, 0.0f, 0.0f, 0.0f};

#pragma unroll
            for (int p = 0; p < 2; p++) {
                uint4 wh = g_Wp_h[p][g][t];
                uint4 wl = g_Wp_l[p][g][t];

                // vr = S @ Re(U)^T rows p*8+g ; vi = S @ Im(U)^T (same rows)
                float ar[4] = {0.0f, 0.0f, 0.0f, 0.0f};
                float ai[4] = {0.0f, 0.0f, 0.0f, 0.0f};
                mma_bf16(ar, ah0, ah1, ah2, ah3, wh.x, wh.y);
                mma_bf16(ai, ah0, ah1, ah2, ah3, wh.z, wh.w);
                mma_bf16(ar, ah0, ah1, ah2, ah3, wl.x, wl.y);
                mma_bf16(ai, ah0, ah1, ah2, ah3, wl.z, wl.w);
                mma_bf16(ar, al0, al1, al2, al3, wh.x, wh.y);
                mma_bf16(ai, al0, al1, al2, al3, wh.z, wh.w);

                // probabilities for i = p*8 + {2t, 2t+1}, rows g and g+8
                float pr0 = fmaf(ar[0], ar[0], ai[0] * ai[0]);  // (g,     i0)
                float pr1 = fmaf(ar[1], ar[1], ai[1] * ai[1]);  // (g,     i0+1)
                float pr2 = fmaf(ar[2], ar[2], ai[2] * ai[2]);  // (g+8,   i0)
                float pr3 = fmaf(ar[3], ar[3], ai[3] * ai[3]);  // (g+8,   i0+1)

                uint32_t ph0, pl0, ph1, pl1;
                split2(pr0, pr1, ph0, pl0);
                split2(pr2, pr3, ph1, pl1);

                uint32_t bsp = p ? bs1 : bs0;
                mma_bf16_k8(ev, ph0, ph1, bsp);
                mma_bf16_k8(ev, pl0, pl1, bsp);
            }

            // ev frag: c0=(g, w=2t), c1=(g,2t+1), c2=(g+8,2t), c3=(g+8,2t+1)
            if (t < 2) {
                int it0 = itemBase + s * 16 + g;
                int it1 = it0 + 8;
                if (it0 < n) o2[it0 * 2 + t] = make_float2(ev[0], ev[1]);
                if (it1 < n) o2[it1 * 2 + t] = make_float2(ev[2], ev[3]);
            }
        }
        // ensure all lanes finished reading staging before group1 overwrites
        __syncwarp();
    }
}

// ---------------------------------------------------------------------------
extern "C" void kernel_launch(void* const* d_in, const int* in_sizes, int n_in,
                              void* d_out, int out_size) {
    const float* patch  = (const float*)d_in[0];   // (B, 4) float32
    const float* params = (const float*)d_in[1];   // (3, 4, 2) float32
    int n = in_sizes[0] / 4;                       // B

    precompute_W_kernel<<<1, 256>>>(params);

    int blocks = (n + 511) / 512;
    vqc_hmma_kernel<<<blocks, 256>>>(
        (const float4*)patch, (float4*)d_out, n);
}

// round 16
// speedup vs baseline: 1.2020x; 1.2020x over previous
#include <cuda_runtime.h>
#include <cuda_bf16.h>
#include <cstdint>
#include <math.h>

#define NQ 4
#define NL 3
#define DIM 16

// Vectorized W fragments: g_WfH[g][t][h] packs the b-fragments of N-tiles
// nt=2h and nt=2h+1 into one uint4:
//   .x = bh[2h][0]   .y = bh[2h][1]   .z = bh[2h+1][0]   .w = bh[2h+1][1]
// where bh[nt][0] = {W[nt*8+g][2t], W[nt*8+g][2t+1]} (bf16x2),
//       bh[nt][1] = {W[nt*8+g][2t+8], W[nt*8+g][2t+9]},
// W = [Re U; Im U] (32 x 16). g_WfL holds the bf16 residual (lo) parts.
__device__ uint4 g_WfH[8][4][2];
__device__ uint4 g_WfL[8][4][2];

// hi/lo bf16 split of a float pair, packed {v0 -> lo half, v1 -> hi half}
__device__ __forceinline__ void split2(float v0, float v1,
                                       uint32_t& h, uint32_t& l) {
    asm("cvt.rn.bf16x2.f32 %0, %1, %2;" : "=r"(h) : "f"(v1), "f"(v0));
    float f0 = __uint_as_float(h << 16);
    float f1 = __uint_as_float(h & 0xFFFF0000u);
    float l0 = v0 - f0;
    float l1 = v1 - f1;
    asm("cvt.rn.bf16x2.f32 %0, %1, %2;" : "=r"(l) : "f"(l1), "f"(l0));
}

// pack two f32 into f16x2 {v0 -> lo half, v1 -> hi half}
__device__ __forceinline__ uint32_t packh2(float v0, float v1) {
    uint32_t r;
    asm("cvt.rn.f16x2.f32 %0, %1, %2;" : "=r"(r) : "f"(v1), "f"(v0));
    return r;
}

// ---------------------------------------------------------------------------
// Prekernel: 256 threads = 16 columns x 16 basis states, one complex
// amplitude per thread (shfl_xor butterflies); then 64 threads repack U into
// the vectorized W fragment layout.
// ---------------------------------------------------------------------------
__global__ void precompute_W_kernel(const float* __restrict__ params) {
    __shared__ float sUr[DIM][DIM], sUi[DIM][DIM];

    const int tid = threadIdx.x;          // 0..255
    const int j = tid >> 4;               // column (initial basis state)
    const int i = tid & 15;               // this thread's basis state index

    float re = (i == j) ? 1.0f : 0.0f;
    float im = 0.0f;

#pragma unroll
    for (int l = 0; l < NL; l++) {
#pragma unroll
        for (int w = 0; w < NQ; w++) {
            const int m = 1 << (3 - w);
            float ty = 0.5f * params[(l * NQ + w) * 2 + 0];
            float sy, cy;
            __sincosf(ty, &sy, &cy);
            float pre = __shfl_xor_sync(0xFFFFFFFFu, re, m);
            float pim = __shfl_xor_sync(0xFFFFFFFFu, im, m);
            if (i & m) {
                re = fmaf(cy, re,  sy * pre);
                im = fmaf(cy, im,  sy * pim);
            } else {
                re = fmaf(cy, re, -sy * pre);
                im = fmaf(cy, im, -sy * pim);
            }
            float tz = 0.5f * params[(l * NQ + w) * 2 + 1];
            float sz, cz;
            __sincosf(tz, &sz, &cz);
            float szs = (i & m) ? sz : -sz;
            float nre = fmaf(cz, re, -szs * im);
            float nim = fmaf(cz, im,  szs * re);
            re = nre;
            im = nim;
        }
#pragma unroll
        for (int w = 0; w < NQ - 1; w++) {
            const int mc = 1 << (3 - w);
            const int mt = 1 << (2 - w);
            float pre = __shfl_xor_sync(0xFFFFFFFFu, re, mt);
            float pim = __shfl_xor_sync(0xFFFFFFFFu, im, mt);
            if (i & mc) { re = pre; im = pim; }
        }
    }

    sUr[i][j] = re;
    sUi[i][j] = im;
    __syncthreads();

    // Repack: 64 threads, one (H, L) uint4 pair each.
    if (tid < 64) {
        const int g = tid >> 3;
        const int t = (tid >> 1) & 3;
        const int h = tid & 1;

        auto Wv = [&](int n, int k) -> float {
            return (n < DIM) ? sUr[n][k] : sUi[n - DIM][k];
        };

        uint4 H, L;
        int n0 = (2 * h) * 8 + g;
        int n1 = (2 * h + 1) * 8 + g;
        split2(Wv(n0, 2 * t),     Wv(n0, 2 * t + 1), H.x, L.x);
        split2(Wv(n0, 2 * t + 8), Wv(n0, 2 * t + 9), H.y, L.y);
        split2(Wv(n1, 2 * t),     Wv(n1, 2 * t + 1), H.z, L.z);
        split2(Wv(n1, 2 * t + 8), Wv(n1, 2 * t + 9), H.w, L.w);
        g_WfH[g][t][h] = H;
        g_WfL[g][t][h] = L;
    }
}

// ---------------------------------------------------------------------------
// HMMA helpers (base-target sm_80+ instructions; no 'a' features)
// ---------------------------------------------------------------------------
__device__ __forceinline__ uint32_t smem_u32(const void* p) {
    uint32_t a;
    asm("{ .reg .u64 t; cvta.to.shared.u64 t, %1; cvt.u32.u64 %0, t; }"
        : "=r"(a) : "l"(p));
    return a;
}

__device__ __forceinline__ void ldmatrix_x4(uint32_t& r0, uint32_t& r1,
                                            uint32_t& r2, uint32_t& r3,
                                            uint32_t addr) {
    asm volatile("ldmatrix.sync.aligned.m8n8.x4.shared.b16 {%0,%1,%2,%3}, [%4];"
                 : "=r"(r0), "=r"(r1), "=r"(r2), "=r"(r3) : "r"(addr));
}

__device__ __forceinline__ void mma_bf16(float* d, uint32_t a0, uint32_t a1,
                                         uint32_t a2, uint32_t a3,
                                         uint32_t b0, uint32_t b1) {
    asm volatile(
        "mma.sync.aligned.m16n8k16.row.col.f32.bf16.bf16.f32 "
        "{%0,%1,%2,%3}, {%4,%5,%6,%7}, {%8,%9}, {%0,%1,%2,%3};"
        : "+f"(d[0]), "+f"(d[1]), "+f"(d[2]), "+f"(d[3])
        : "r"(a0), "r"(a1), "r"(a2), "r"(a3), "r"(b0), "r"(b1));
}

__device__ __forceinline__ void mma_f16(float* d, uint32_t a0, uint32_t a1,
                                        uint32_t a2, uint32_t a3,
                                        uint32_t b0, uint32_t b1) {
    asm volatile(
        "mma.sync.aligned.m16n8k16.row.col.f32.f16.f16.f32 "
        "{%0,%1,%2,%3}, {%4,%5,%6,%7}, {%8,%9}, {%0,%1,%2,%3};"
        : "+f"(d[0]), "+f"(d[1]), "+f"(d[2]), "+f"(d[3])
        : "r"(a0), "r"(a1), "r"(a2), "r"(a3), "r"(b0), "r"(b1));
}

// ---------------------------------------------------------------------------
// Main kernel: 64 items/warp as two sequential 32-item groups reusing one
// 16KB staging buffer (R12 structure). Changes vs R12:
//   - W fragments loaded as 4 LDG.128 (vectorized) instead of 16 LDG.32
//   - EV stage: P rounded to fp16 (Z=+-1 exact in fp16), ONE f16 MMA
//     replaces bf16 hi/lo split + 2 MMAs. Error ~2^-12 * sum(p) <= 2.4e-4.
// A-fragment map for EV MMA (FIXED vs R15):
//   a0 = rows 0-7,k0..7  = (prA,prB) = P(g, 2t,2t+1)
//   a1 = rows 8-15,k0..7 = (prC,prD) = P(g+8, 2t,2t+1)
//   a2 = rows 0-7,k8..15 = (prE,prF) = P(g, 8+2t,9+2t)
//   a3 = rows 8-15,k8..15= (prG,prH) = P(g+8, 8+2t,9+2t)
// ---------------------------------------------------------------------------
__global__ __launch_bounds__(256) void vqc_hmma_kernel(
    const float4* __restrict__ patch, float4* __restrict__ out, int n) {
    // per-warp staging: [8 warps][hi/lo][32 rows][8 u32]  (16 KB)
    __shared__ __align__(16) uint32_t stage[8][2][32][8];

    const int tid = threadIdx.x;
    const int wid = tid >> 5;
    const int lane = tid & 31;
    const int g = lane >> 2;      // 0..7
    const int t = lane & 3;       // 0..3

    const int itemBase = blockIdx.x * 512 + wid * 64;

    // ---- W (B) fragments: 4 vectorized loads, hoisted for all 4 s-tiles ----
    const uint4 wh0 = g_WfH[g][t][0];   // nt0: .x,.y   nt1: .z,.w
    const uint4 wh1 = g_WfH[g][t][1];   // nt2: .x,.y   nt3: .z,.w
    const uint4 wl0 = g_WfL[g][t][0];
    const uint4 wl1 = g_WfL[g][t][1];

    // ---- sign-matrix B fragment (Z[k=i][n=w], exact +-1 fp16), hoisted ----
    uint32_t bs0, bs1;
    {
        auto enc = [&](int i) -> uint32_t {
            if (g >= 4) return 0u;  // unused n columns
            return (((i >> (3 - g)) & 1) ? 0xBC00u : 0x3C00u);
        };
        bs0 = enc(2 * t) | (enc(2 * t + 1) << 16);
        bs1 = enc(2 * t + 8) | (enc(2 * t + 9) << 16);
    }

    float2* o2 = reinterpret_cast<float2*>(out);

#pragma unroll
    for (int u = 0; u < 2; u++) {
        // ---- load this group's patch and build s[16] hi/lo, stage row=lane --
        {
            int item = itemBase + u * 32 + lane;
            float4 p = patch[item < n ? item : (n - 1)];
            float s0, c0, s1, c1, s2, c2, s3, c3;
            __sincosf(0.5f * p.x, &s0, &c0);
            __sincosf(0.5f * p.y, &s1, &c1);
            __sincosf(0.5f * p.z, &s2, &c2);
            __sincosf(0.5f * p.w, &s3, &c3);
            float qa[4] = {c0 * c1, c0 * s1, s0 * c1, s0 * s1};
            float qb[4] = {c2 * c3, c2 * s3, s2 * c3, s2 * s3};

            uint32_t hi[8], lo[8];
#pragma unroll
            for (int c = 0; c < 8; c++) {
                int k0 = 2 * c, k1 = 2 * c + 1;
                float v0 = qa[k0 >> 2] * qb[k0 & 3];
                float v1 = qa[k1 >> 2] * qb[k1 & 3];
                split2(v0, v1, hi[c], lo[c]);
            }
            uint4* dh = reinterpret_cast<uint4*>(&stage[wid][0][lane][0]);
            uint4* dl = reinterpret_cast<uint4*>(&stage[wid][1][lane][0]);
            dh[0] = make_uint4(hi[0], hi[1], hi[2], hi[3]);
            dh[1] = make_uint4(hi[4], hi[5], hi[6], hi[7]);
            dl[0] = make_uint4(lo[0], lo[1], lo[2], lo[3]);
            dl[1] = make_uint4(lo[4], lo[5], lo[6], lo[7]);
        }
        __syncwarp();

#pragma unroll
        for (int sl = 0; sl < 2; sl++) {
            const int s = u * 2 + sl;     // global tile index (item block)
            uint32_t ah0, ah1, ah2, ah3, al0, al1, al2, al3;
            {
                int mrow = sl * 16 + (lane & 15);
                int chunk = (lane >> 4);
                uint32_t addrh = smem_u32(&stage[wid][0][mrow][chunk * 4]);
                uint32_t addrl = smem_u32(&stage[wid][1][mrow][chunk * 4]);
                ldmatrix_x4(ah0, ah1, ah2, ah3, addrh);
                ldmatrix_x4(al0, al1, al2, al3, addrl);
            }

            float acc[4][4];
#pragma unroll
            for (int nt = 0; nt < 4; nt++)
                acc[nt][0] = acc[nt][1] = acc[nt][2] = acc[nt][3] = 0.0f;

            // nt0
            mma_bf16(acc[0], ah0, ah1, ah2, ah3, wh0.x, wh0.y);
            mma_bf16(acc[0], ah0, ah1, ah2, ah3, wl0.x, wl0.y);
            mma_bf16(acc[0], al0, al1, al2, al3, wh0.x, wh0.y);
            // nt1
            mma_bf16(acc[1], ah0, ah1, ah2, ah3, wh0.z, wh0.w);
            mma_bf16(acc[1], ah0, ah1, ah2, ah3, wl0.z, wl0.w);
            mma_bf16(acc[1], al0, al1, al2, al3, wh0.z, wh0.w);
            // nt2
            mma_bf16(acc[2], ah0, ah1, ah2, ah3, wh1.x, wh1.y);
            mma_bf16(acc[2], ah0, ah1, ah2, ah3, wl1.x, wl1.y);
            mma_bf16(acc[2], al0, al1, al2, al3, wh1.x, wh1.y);
            // nt3
            mma_bf16(acc[3], ah0, ah1, ah2, ah3, wh1.z, wh1.w);
            mma_bf16(acc[3], ah0, ah1, ah2, ah3, wl1.z, wl1.w);
            mma_bf16(acc[3], al0, al1, al2, al3, wh1.z, wh1.w);

            // pr matrix P[16 items, 16 i] in exact A-fragment layout
            // acc[nt][j]: c0=(g, i=nt8+2t) c1=(g, nt8+2t+1) c2=(g+8, ..) c3
            float prA = fmaf(acc[0][0], acc[0][0], acc[2][0] * acc[2][0]);  // (g,    2t)
            float prB = fmaf(acc[0][1], acc[0][1], acc[2][1] * acc[2][1]);  // (g,    2t+1)
            float prC = fmaf(acc[0][2], acc[0][2], acc[2][2] * acc[2][2]);  // (g+8,  2t)
            float prD = fmaf(acc[0][3], acc[0][3], acc[2][3] * acc[2][3]);  // (g+8,  2t+1)
            float prE = fmaf(acc[1][0], acc[1][0], acc[3][0] * acc[3][0]);  // (g,    8+2t)
            float prF = fmaf(acc[1][1], acc[1][1], acc[3][1] * acc[3][1]);  // (g,    9+2t)
            float prG = fmaf(acc[1][2], acc[1][2], acc[3][2] * acc[3][2]);  // (g+8,  8+2t)
            float prH = fmaf(acc[1][3], acc[1][3], acc[3][3] * acc[3][3]);  // (g+8,  9+2t)

            // fp16 A-fragment of P (Z=+-1 exact; fp32 accumulate) — FIXED map
            uint32_t pa0 = packh2(prA, prB);   // rows 0-7,  k 0-7
            uint32_t pa1 = packh2(prC, prD);   // rows 8-15, k 0-7
            uint32_t pa2 = packh2(prE, prF);   // rows 0-7,  k 8-15
            uint32_t pa3 = packh2(prG, prH);   // rows 8-15, k 8-15

            float ev[4] = {0.0f, 0.0f, 0.0f, 0.0f};
            mma_f16(ev, pa0, pa1, pa2, pa3, bs0, bs1);

            // ev frag: c0=(g, w=2t), c1=(g,2t+1), c2=(g+8,2t), c3=(g+8,2t+1)
            if (t < 2) {
                int it0 = itemBase + s * 16 + g;
                int it1 = it0 + 8;
                if (it0 < n) o2[it0 * 2 + t] = make_float2(ev[0], ev[1]);
                if (it1 < n) o2[it1 * 2 + t] = make_float2(ev[2], ev[3]);
            }
        }
        // ensure all lanes finished reading staging before group1 overwrites
        __syncwarp();
    }
}

// ---------------------------------------------------------------------------
extern "C" void kernel_launch(void* const* d_in, const int* in_sizes, int n_in,
                              void* d_out, int out_size) {
    const float* patch  = (const float*)d_in[0];   // (B, 4) float32
    const float* params = (const float*)d_in[1];   // (3, 4, 2) float32
    int n = in_sizes[0] / 4;                       // B

    precompute_W_kernel<<<1, 256>>>(params);

    int blocks = (n + 511) / 512;
    vqc_hmma_kernel<<<blocks, 256>>>(
        (const float4*)patch, (float4*)d_out, n);
}